// round 7
// baseline (speedup 1.0000x reference)
#include <cuda_runtime.h>
#include <cuda_bf16.h>
#include <math.h>

// ---------------- problem constants ----------------
#define NN    50000
#define EE    800000
#define EP    850000          // EE + NN self loops
#define INC   1024
#define H1    4
#define C1    64
#define HC1   256             // H1*C1
#define OC    64
#define NEG_SLOPE 0.2f

#define SB_T 1024             // single-block scan threads

// ---------------- scratch (device globals) ----------------
__device__ float  g_h1[(size_t)NN * HC1];
__device__ float  g_x2[(size_t)NN * HC1];
__device__ float  g_as1[NN * H1];
__device__ float  g_ad1[NN * H1];
__device__ float4 g_alpha1[EP];               // per-edge exp values (4 heads), CSR order
__device__ float4 g_rd1[NN];                  // reciprocal softmax denominators

__device__ float  g_h2[(size_t)NN * OC];
__device__ float  g_as2[NN];
__device__ float  g_ad2[NN];
__device__ float  g_alpha2[EP];
__device__ float  g_rd2[NN];

// CSR
__device__ int g_deg[NN];
__device__ int g_rowptr[NN + 1];
__device__ int g_cursor[NN];
__device__ int g_srcidx[EP];

__device__ __forceinline__ unsigned f2tf32(float f) {
    unsigned r;
    asm("cvt.rna.tf32.f32 %0, %1;" : "=r"(r) : "f"(f));
    return r;
}

// ================= init + CSR construction =================
__global__ void k_zero() {
    int i = blockIdx.x * blockDim.x + threadIdx.x;
    if (i >= NN) return;
    g_deg[i] = 0;
    g_as2[i] = 0.f; g_ad2[i] = 0.f;
    float4 z = make_float4(0.f, 0.f, 0.f, 0.f);
    ((float4*)g_as1)[i] = z;
    ((float4*)g_ad1)[i] = z;
}
__global__ void k_count(const int* __restrict__ ei) {
    int e = blockIdx.x * blockDim.x + threadIdx.x;
    if (e >= EP) return;
    int dn = (e < EE) ? ei[EE + e] : (e - EE);
    atomicAdd(&g_deg[dn], 1);
}
// single-block scan: rowptr (exclusive->inclusive) + cursor init
__global__ __launch_bounds__(SB_T) void k_scan_all() {
    __shared__ int ssum[SB_T];
    int tid = threadIdx.x;
    const int CH = (NN + SB_T - 1) / SB_T;
    int beg = tid * CH;
    int end = (beg + CH < NN) ? beg + CH : NN;
    int s = 0;
    for (int i = beg; i < end; i++) s += g_deg[i];
    ssum[tid] = s;
    __syncthreads();
    #pragma unroll
    for (int off = 1; off < SB_T; off <<= 1) {
        int t = (tid >= off) ? ssum[tid - off] : 0;
        __syncthreads();
        ssum[tid] += t;
        __syncthreads();
    }
    int run = (tid > 0) ? ssum[tid - 1] : 0;
    if (tid == 0) g_rowptr[0] = 0;
    for (int i = beg; i < end; i++) {
        g_cursor[i] = run;
        run += g_deg[i];
        g_rowptr[i + 1] = run;
    }
}
__global__ void k_scatter(const int* __restrict__ ei) {
    int e = blockIdx.x * blockDim.x + threadIdx.x;
    if (e >= EP) return;
    int s, dn;
    if (e < EE) { s = ei[e]; dn = ei[EE + e]; }
    else        { s = e - EE; dn = s; }
    int pos = atomicAdd(&g_cursor[dn], 1);
    g_srcidx[pos] = s;
}

// ============= TF32 GEMM + fused attention-coefficient epilogue ==============
// smem layout: per 8-k-group, k and k+4 interleaved -> LDS.64 fragment loads.
// word index for k col kc: (kc & 24) + ((kc&4)?1:0) + 2*(kc&3)
#define TBM 128
#define TBN 128
#define TBK 32
#define TSS 40
#define GEMM_SMEM_BYTES (4 * TBM * TSS * 4)   // 2 bufs x (A,B) x 128x40 u32

__global__ __launch_bounds__(256) void k_tf32gemm(
    const float* __restrict__ A, const float* __restrict__ B,
    float* __restrict__ C, int M, int N, int K,
    const float* __restrict__ avs, const float* __restrict__ avd,
    float* __restrict__ as_out, float* __restrict__ ad_out, int heads)
{
    extern __shared__ unsigned smem_u[];
    unsigned* Abase = smem_u;                    // [2][TBM][TSS]
    unsigned* Bbase = smem_u + 2 * TBM * TSS;    // [2][TBN][TSS]

    int tid = threadIdx.x;
    int bm = blockIdx.y * TBM, bn = blockIdx.x * TBN;
    int wid = tid >> 5, lane = tid & 31;
    int wm = (wid >> 2) * 64;
    int wn = (wid & 3) * 32;
    int g  = lane >> 2;
    int t4 = lane & 3;

    int r0 = tid >> 3;
    int c4 = (tid & 7) * 4;
    int wbase = (c4 & 24) + ((c4 & 4) ? 1 : 0);   // interleaved store base

    float c[4][4][4];
    #pragma unroll
    for (int i = 0; i < 4; i++)
        #pragma unroll
        for (int j = 0; j < 4; j++)
            #pragma unroll
            for (int r = 0; r < 4; r++) c[i][j][r] = 0.f;

    const float4 zero4 = make_float4(0.f, 0.f, 0.f, 0.f);
    float4 pa[4], pb[4];
    int nt = K / TBK;

    // fetch + store tile 0 -> buf 0
    #pragma unroll
    for (int i = 0; i < 4; i++) {
        int ar = bm + r0 + 32 * i;
        pa[i] = (ar < M) ? *(const float4*)(A + (size_t)ar * K + c4) : zero4;
        int br = bn + r0 + 32 * i;
        pb[i] = (br < N) ? *(const float4*)(B + (size_t)br * K + c4) : zero4;
    }
    {
        unsigned* Ab = Abase;
        unsigned* Bb = Bbase;
        #pragma unroll
        for (int i = 0; i < 4; i++) {
            int rr = r0 + 32 * i;
            unsigned* ap = Ab + rr * TSS + wbase;
            unsigned* bp = Bb + rr * TSS + wbase;
            ap[0] = f2tf32(pa[i].x); ap[2] = f2tf32(pa[i].y);
            ap[4] = f2tf32(pa[i].z); ap[6] = f2tf32(pa[i].w);
            bp[0] = f2tf32(pb[i].x); bp[2] = f2tf32(pb[i].y);
            bp[4] = f2tf32(pb[i].z); bp[6] = f2tf32(pb[i].w);
        }
    }
    __syncthreads();

    for (int t = 0; t < nt; t++) {
        int cur = t & 1;
        bool more = (t + 1 < nt);
        if (more) {
            int k0 = (t + 1) * TBK;
            #pragma unroll
            for (int i = 0; i < 4; i++) {
                int ar = bm + r0 + 32 * i;
                pa[i] = (ar < M) ? *(const float4*)(A + (size_t)ar * K + k0 + c4) : zero4;
                int br = bn + r0 + 32 * i;
                pb[i] = (br < N) ? *(const float4*)(B + (size_t)br * K + k0 + c4) : zero4;
            }
        }
        const unsigned* Ab = Abase + cur * TBM * TSS;
        const unsigned* Bb = Bbase + cur * TBM * TSS;
        #pragma unroll
        for (int ks = 0; ks < 4; ks++) {
            int k8 = ks * 8 + 2 * t4;
            unsigned af[4][4], bf[4][2];
            #pragma unroll
            for (int mt = 0; mt < 4; mt++) {
                int row = wm + mt * 16 + g;
                uint2 lo = *(const uint2*)&Ab[row * TSS + k8];        // (k, k+4)
                uint2 hi = *(const uint2*)&Ab[(row + 8) * TSS + k8];
                af[mt][0] = lo.x; af[mt][2] = lo.y;
                af[mt][1] = hi.x; af[mt][3] = hi.y;
            }
            #pragma unroll
            for (int ntj = 0; ntj < 4; ntj++) {
                int col = wn + ntj * 8 + g;
                uint2 bb = *(const uint2*)&Bb[col * TSS + k8];
                bf[ntj][0] = bb.x; bf[ntj][1] = bb.y;
            }
            #pragma unroll
            for (int mt = 0; mt < 4; mt++)
                #pragma unroll
                for (int ntj = 0; ntj < 4; ntj++) {
                    asm volatile(
                        "mma.sync.aligned.m16n8k8.row.col.f32.tf32.tf32.f32 "
                        "{%0,%1,%2,%3}, {%4,%5,%6,%7}, {%8,%9}, {%0,%1,%2,%3};"
                        : "+f"(c[mt][ntj][0]), "+f"(c[mt][ntj][1]),
                          "+f"(c[mt][ntj][2]), "+f"(c[mt][ntj][3])
                        : "r"(af[mt][0]), "r"(af[mt][1]), "r"(af[mt][2]), "r"(af[mt][3]),
                          "r"(bf[ntj][0]), "r"(bf[ntj][1]));
                }
        }
        if (more) {
            int nx = cur ^ 1;
            unsigned* Aw = Abase + nx * TBM * TSS;
            unsigned* Bw = Bbase + nx * TBM * TSS;
            #pragma unroll
            for (int i = 0; i < 4; i++) {
                int rr = r0 + 32 * i;
                unsigned* ap = Aw + rr * TSS + wbase;
                unsigned* bp = Bw + rr * TSS + wbase;
                ap[0] = f2tf32(pa[i].x); ap[2] = f2tf32(pa[i].y);
                ap[4] = f2tf32(pa[i].z); ap[6] = f2tf32(pa[i].w);
                bp[0] = f2tf32(pb[i].x); bp[2] = f2tf32(pb[i].y);
                bp[4] = f2tf32(pb[i].z); bp[6] = f2tf32(pb[i].w);
            }
            __syncthreads();
        }
    }

    // ---- C store ----
    #pragma unroll
    for (int mt = 0; mt < 4; mt++) {
        int row0 = bm + wm + mt * 16 + g;
        #pragma unroll
        for (int ntj = 0; ntj < 4; ntj++) {
            int col = bn + wn + ntj * 8 + t4 * 2;
            if (row0 < M && col + 1 < N) {
                C[(size_t)row0 * N + col]     = c[mt][ntj][0];
                C[(size_t)row0 * N + col + 1] = c[mt][ntj][1];
            }
            if (row0 + 8 < M && col + 1 < N) {
                C[(size_t)(row0 + 8) * N + col]     = c[mt][ntj][2];
                C[(size_t)(row0 + 8) * N + col + 1] = c[mt][ntj][3];
            }
        }
    }

    // ---- fused attention-coefficient partials ----
    int head = (bn + wn) >> 6;
    if (head < heads) {
        float asac[4][2] = {}, adac[4][2] = {};
        #pragma unroll
        for (int mt = 0; mt < 4; mt++)
            #pragma unroll
            for (int ntj = 0; ntj < 4; ntj++) {
                int colb = bn + wn + ntj * 8 + t4 * 2;
                if (colb + 1 < N) {
                    float s0 = avs[colb], s1 = avs[colb + 1];
                    float d0 = avd[colb], d1 = avd[colb + 1];
                    asac[mt][0] += c[mt][ntj][0] * s0 + c[mt][ntj][1] * s1;
                    adac[mt][0] += c[mt][ntj][0] * d0 + c[mt][ntj][1] * d1;
                    asac[mt][1] += c[mt][ntj][2] * s0 + c[mt][ntj][3] * s1;
                    adac[mt][1] += c[mt][ntj][2] * d0 + c[mt][ntj][3] * d1;
                }
            }
        #pragma unroll
        for (int mt = 0; mt < 4; mt++)
            #pragma unroll
            for (int hf = 0; hf < 2; hf++) {
                float v = asac[mt][hf];
                float w = adac[mt][hf];
                v += __shfl_xor_sync(0xFFFFFFFFu, v, 1);
                v += __shfl_xor_sync(0xFFFFFFFFu, v, 2);
                w += __shfl_xor_sync(0xFFFFFFFFu, w, 1);
                w += __shfl_xor_sync(0xFFFFFFFFu, w, 2);
                int row = bm + wm + mt * 16 + g + hf * 8;
                if (t4 == 0 && row < M) {
                    atomicAdd(&as_out[row * heads + head], v);
                    atomicAdd(&ad_out[row * heads + head], w);
                }
            }
    }
}

// ---------------- softmax layer 1: warp per dst node, 4 heads ----------------
__global__ __launch_bounds__(256) void k_softmax1()
{
    int w = (blockIdx.x * blockDim.x + threadIdx.x) >> 5;
    int lane = threadIdx.x & 31;
    if (w >= NN) return;
    int beg = g_rowptr[w], end = g_rowptr[w + 1];
    const float4* as4 = (const float4*)g_as1;
    float4 adv = ((const float4*)g_ad1)[w];
    float4 mx = make_float4(-1e30f, -1e30f, -1e30f, -1e30f);
    for (int i = beg + lane; i < end; i += 32) {
        float4 e = as4[g_srcidx[i]];
        e.x += adv.x; e.y += adv.y; e.z += adv.z; e.w += adv.w;
        e.x = (e.x > 0.f) ? e.x : NEG_SLOPE * e.x;
        e.y = (e.y > 0.f) ? e.y : NEG_SLOPE * e.y;
        e.z = (e.z > 0.f) ? e.z : NEG_SLOPE * e.z;
        e.w = (e.w > 0.f) ? e.w : NEG_SLOPE * e.w;
        g_alpha1[i] = e;
        mx.x = fmaxf(mx.x, e.x); mx.y = fmaxf(mx.y, e.y);
        mx.z = fmaxf(mx.z, e.z); mx.w = fmaxf(mx.w, e.w);
    }
    #pragma unroll
    for (int o = 16; o > 0; o >>= 1) {
        mx.x = fmaxf(mx.x, __shfl_xor_sync(0xFFFFFFFFu, mx.x, o));
        mx.y = fmaxf(mx.y, __shfl_xor_sync(0xFFFFFFFFu, mx.y, o));
        mx.z = fmaxf(mx.z, __shfl_xor_sync(0xFFFFFFFFu, mx.z, o));
        mx.w = fmaxf(mx.w, __shfl_xor_sync(0xFFFFFFFFu, mx.w, o));
    }
    float4 sum = make_float4(0.f, 0.f, 0.f, 0.f);
    for (int i = beg + lane; i < end; i += 32) {
        float4 e = g_alpha1[i];
        e.x = __expf(e.x - mx.x); e.y = __expf(e.y - mx.y);
        e.z = __expf(e.z - mx.z); e.w = __expf(e.w - mx.w);
        g_alpha1[i] = e;
        sum.x += e.x; sum.y += e.y; sum.z += e.z; sum.w += e.w;
    }
    #pragma unroll
    for (int o = 16; o > 0; o >>= 1) {
        sum.x += __shfl_xor_sync(0xFFFFFFFFu, sum.x, o);
        sum.y += __shfl_xor_sync(0xFFFFFFFFu, sum.y, o);
        sum.z += __shfl_xor_sync(0xFFFFFFFFu, sum.z, o);
        sum.w += __shfl_xor_sync(0xFFFFFFFFu, sum.w, o);
    }
    if (lane == 0)
        g_rd1[w] = make_float4(1.f / sum.x, 1.f / sum.y, 1.f / sum.z, 1.f / sum.w);
}

// ---------------- softmax layer 2 --------------------------------------------
__global__ __launch_bounds__(256) void k_softmax2()
{
    int w = (blockIdx.x * blockDim.x + threadIdx.x) >> 5;
    int lane = threadIdx.x & 31;
    if (w >= NN) return;
    int beg = g_rowptr[w], end = g_rowptr[w + 1];
    float adv = g_ad2[w];
    float mx = -1e30f;
    for (int i = beg + lane; i < end; i += 32) {
        float e = g_as2[g_srcidx[i]] + adv;
        e = (e > 0.f) ? e : NEG_SLOPE * e;
        g_alpha2[i] = e;
        mx = fmaxf(mx, e);
    }
    #pragma unroll
    for (int o = 16; o > 0; o >>= 1)
        mx = fmaxf(mx, __shfl_xor_sync(0xFFFFFFFFu, mx, o));
    float sum = 0.f;
    for (int i = beg + lane; i < end; i += 32) {
        float e = __expf(g_alpha2[i] - mx);
        g_alpha2[i] = e;
        sum += e;
    }
    #pragma unroll
    for (int o = 16; o > 0; o >>= 1)
        sum += __shfl_xor_sync(0xFFFFFFFFu, sum, o);
    if (lane == 0) g_rd2[w] = 1.f / sum;
}

// ---- aggregation layer 1: 64 threads per dst row, fused +b1 and elu ---------
__global__ __launch_bounds__(256) void k_agg1(const float* __restrict__ b1)
{
    int row = blockIdx.x * 4 + (threadIdx.x >> 6);
    if (row >= NN) return;
    int q = threadIdx.x & 63;
    int head = q >> 4;
    int beg = g_rowptr[row], end = g_rowptr[row + 1];
    float4 rdv = g_rd1[row];
    float rd = (head == 0) ? rdv.x : (head == 1) ? rdv.y : (head == 2) ? rdv.z : rdv.w;
    float4 acc0 = make_float4(0.f, 0.f, 0.f, 0.f);
    float4 acc1 = make_float4(0.f, 0.f, 0.f, 0.f);
    int i = beg;
    for (; i + 2 <= end; i += 2) {
        int s0 = g_srcidx[i], s1 = g_srcidx[i + 1];
        float4 a40 = g_alpha1[i], a41 = g_alpha1[i + 1];
        float a0 = (head == 0) ? a40.x : (head == 1) ? a40.y : (head == 2) ? a40.z : a40.w;
        float a1 = (head == 0) ? a41.x : (head == 1) ? a41.y : (head == 2) ? a41.z : a41.w;
        float4 h0 = *(const float4*)(g_h1 + (size_t)s0 * HC1 + q * 4);
        float4 h1 = *(const float4*)(g_h1 + (size_t)s1 * HC1 + q * 4);
        acc0.x += a0 * h0.x; acc0.y += a0 * h0.y; acc0.z += a0 * h0.z; acc0.w += a0 * h0.w;
        acc1.x += a1 * h1.x; acc1.y += a1 * h1.y; acc1.z += a1 * h1.z; acc1.w += a1 * h1.w;
    }
    if (i < end) {
        int s0 = g_srcidx[i];
        float4 a40 = g_alpha1[i];
        float a0 = (head == 0) ? a40.x : (head == 1) ? a40.y : (head == 2) ? a40.z : a40.w;
        float4 h0 = *(const float4*)(g_h1 + (size_t)s0 * HC1 + q * 4);
        acc0.x += a0 * h0.x; acc0.y += a0 * h0.y; acc0.z += a0 * h0.z; acc0.w += a0 * h0.w;
    }
    float4 acc = make_float4((acc0.x + acc1.x) * rd, (acc0.y + acc1.y) * rd,
                             (acc0.z + acc1.z) * rd, (acc0.w + acc1.w) * rd);
    float4 bb = *(const float4*)(b1 + q * 4);
    acc.x += bb.x; acc.y += bb.y; acc.z += bb.z; acc.w += bb.w;
    acc.x = (acc.x > 0.f) ? acc.x : expm1f(acc.x);
    acc.y = (acc.y > 0.f) ? acc.y : expm1f(acc.y);
    acc.z = (acc.z > 0.f) ? acc.z : expm1f(acc.z);
    acc.w = (acc.w > 0.f) ? acc.w : expm1f(acc.w);
    *(float4*)(g_x2 + (size_t)row * HC1 + q * 4) = acc;
}

// ---- aggregation layer 2: 16 threads per dst row, fused +b2, writes d_out ---
__global__ __launch_bounds__(256) void k_agg2(const float* __restrict__ b2,
                                              float* __restrict__ out)
{
    int row = blockIdx.x * 16 + (threadIdx.x >> 4);
    if (row >= NN) return;
    int q = threadIdx.x & 15;
    int beg = g_rowptr[row], end = g_rowptr[row + 1];
    float rd = g_rd2[row];
    float4 acc0 = make_float4(0.f, 0.f, 0.f, 0.f);
    float4 acc1 = make_float4(0.f, 0.f, 0.f, 0.f);
    int i = beg;
    for (; i + 2 <= end; i += 2) {
        int s0 = g_srcidx[i], s1 = g_srcidx[i + 1];
        float a0 = g_alpha2[i], a1 = g_alpha2[i + 1];
        float4 h0 = *(const float4*)(g_h2 + (size_t)s0 * OC + q * 4);
        float4 h1 = *(const float4*)(g_h2 + (size_t)s1 * OC + q * 4);
        acc0.x += a0 * h0.x; acc0.y += a0 * h0.y; acc0.z += a0 * h0.z; acc0.w += a0 * h0.w;
        acc1.x += a1 * h1.x; acc1.y += a1 * h1.y; acc1.z += a1 * h1.z; acc1.w += a1 * h1.w;
    }
    if (i < end) {
        int s0 = g_srcidx[i];
        float a0 = g_alpha2[i];
        float4 h0 = *(const float4*)(g_h2 + (size_t)s0 * OC + q * 4);
        acc0.x += a0 * h0.x; acc0.y += a0 * h0.y; acc0.z += a0 * h0.z; acc0.w += a0 * h0.w;
    }
    float4 bb = *(const float4*)(b2 + q * 4);
    float4 acc = make_float4((acc0.x + acc1.x) * rd + bb.x, (acc0.y + acc1.y) * rd + bb.y,
                             (acc0.z + acc1.z) * rd + bb.z, (acc0.w + acc1.w) * rd + bb.w);
    *(float4*)(out + (size_t)row * OC + q * 4) = acc;
}

// =============================================================================
extern "C" void kernel_launch(void* const* d_in, const int* in_sizes, int n_in,
                              void* d_out, int out_size)
{
    const float* x     = (const float*)d_in[0];
    const int*   ei    = (const int*)d_in[1];
    const float* W1    = (const float*)d_in[2];
    const float* a_s1  = (const float*)d_in[3];
    const float* a_d1  = (const float*)d_in[4];
    const float* b1    = (const float*)d_in[5];
    const float* W2    = (const float*)d_in[6];
    const float* a_s2  = (const float*)d_in[7];
    const float* a_d2  = (const float*)d_in[8];
    const float* b2    = (const float*)d_in[9];
    float*       out   = (float*)d_out;

    float *h1, *x2, *as1, *ad1, *h2, *as2, *ad2;
    cudaGetSymbolAddress((void**)&h1,  g_h1);
    cudaGetSymbolAddress((void**)&x2,  g_x2);
    cudaGetSymbolAddress((void**)&as1, g_as1);
    cudaGetSymbolAddress((void**)&ad1, g_ad1);
    cudaGetSymbolAddress((void**)&h2,  g_h2);
    cudaGetSymbolAddress((void**)&as2, g_as2);
    cudaGetSymbolAddress((void**)&ad2, g_ad2);

    cudaFuncSetAttribute(k_tf32gemm,
                         cudaFuncAttributeMaxDynamicSharedMemorySize, GEMM_SMEM_BYTES);

    // ---- init + CSR build ----
    k_zero<<<(NN + 255) / 256, 256>>>();
    k_count<<<(EP + 255) / 256, 256>>>(ei);
    k_scan_all<<<1, SB_T>>>();
    k_scatter<<<(EP + 255) / 256, 256>>>(ei);

    // ---- layer 1 ----
    {
        dim3 grid((HC1 + TBN - 1) / TBN, (NN + TBM - 1) / TBM);
        k_tf32gemm<<<grid, 256, GEMM_SMEM_BYTES>>>(x, W1, h1, NN, HC1, INC,
                                                   a_s1, a_d1, as1, ad1, H1);
    }
    k_softmax1<<<(NN * 32 + 255) / 256, 256>>>();
    k_agg1<<<(NN + 3) / 4, 256>>>(b1);

    // ---- layer 2 ----
    {
        dim3 grid((OC + TBN - 1) / TBN, (NN + TBM - 1) / TBM);
        k_tf32gemm<<<grid, 256, GEMM_SMEM_BYTES>>>(x2, W2, h2, NN, OC, HC1,
                                                   a_s2, a_d2, as2, ad2, 1);
    }
    k_softmax2<<<(NN * 32 + 255) / 256, 256>>>();
    k_agg2<<<(NN + 15) / 16, 256>>>(b2, out);
}

// round 8
// speedup vs baseline: 1.1433x; 1.1433x over previous
#include <cuda_runtime.h>
#include <cuda_bf16.h>
#include <math.h>

// ---------------- problem constants ----------------
#define NN    50000
#define EE    800000
#define EP    850000          // EE + NN self loops
#define INC   1024
#define H1    4
#define C1    64
#define HC1   256             // H1*C1
#define OC    64
#define NEG_SLOPE 0.2f

#define SB_T 1024             // single-block scan threads

// ---------------- scratch (device globals) ----------------
__device__ float  g_h1[(size_t)NN * HC1];
__device__ float  g_x2[(size_t)NN * HC1];
__device__ float  g_as1[NN * H1];
__device__ float  g_ad1[NN * H1];
__device__ float4 g_alpha1[EP];               // per-edge exp values (4 heads), CSR order
__device__ float4 g_rd1[NN];                  // reciprocal softmax denominators

__device__ float  g_h2[(size_t)NN * OC];
__device__ float  g_as2[NN];
__device__ float  g_ad2[NN];
__device__ float  g_alpha2[EP];
__device__ float  g_rd2[NN];

// CSR
__device__ int g_deg[NN];
__device__ int g_rowptr[NN + 1];
__device__ int g_cursor[NN];
__device__ int g_srcidx[EP];

__device__ __forceinline__ unsigned f2tf32(float f) {
    unsigned r;
    asm("cvt.rna.tf32.f32 %0, %1;" : "=r"(r) : "f"(f));
    return r;
}

// ================= init + CSR construction =================
__global__ void k_zero() {
    int i = blockIdx.x * blockDim.x + threadIdx.x;
    if (i >= NN) return;
    g_deg[i] = 0;
    g_as2[i] = 0.f; g_ad2[i] = 0.f;
    float4 z = make_float4(0.f, 0.f, 0.f, 0.f);
    ((float4*)g_as1)[i] = z;
    ((float4*)g_ad1)[i] = z;
}
__global__ void k_count(const int* __restrict__ ei) {
    int e = blockIdx.x * blockDim.x + threadIdx.x;
    if (e >= EP) return;
    int dn = (e < EE) ? ei[EE + e] : (e - EE);
    atomicAdd(&g_deg[dn], 1);
}
// single-block scan: rowptr + cursor init
__global__ __launch_bounds__(SB_T) void k_scan_all() {
    __shared__ int ssum[SB_T];
    int tid = threadIdx.x;
    const int CH = (NN + SB_T - 1) / SB_T;
    int beg = tid * CH;
    int end = (beg + CH < NN) ? beg + CH : NN;
    int s = 0;
    for (int i = beg; i < end; i++) s += g_deg[i];
    ssum[tid] = s;
    __syncthreads();
    #pragma unroll
    for (int off = 1; off < SB_T; off <<= 1) {
        int t = (tid >= off) ? ssum[tid - off] : 0;
        __syncthreads();
        ssum[tid] += t;
        __syncthreads();
    }
    int run = (tid > 0) ? ssum[tid - 1] : 0;
    if (tid == 0) g_rowptr[0] = 0;
    for (int i = beg; i < end; i++) {
        g_cursor[i] = run;
        run += g_deg[i];
        g_rowptr[i + 1] = run;
    }
}
__global__ void k_scatter(const int* __restrict__ ei) {
    int e = blockIdx.x * blockDim.x + threadIdx.x;
    if (e >= EP) return;
    int s, dn;
    if (e < EE) { s = ei[e]; dn = ei[EE + e]; }
    else        { s = e - EE; dn = s; }
    int pos = atomicAdd(&g_cursor[dn], 1);
    g_srcidx[pos] = s;
}

// ============= TF32 GEMM + fused attention-coefficient epilogue ==============
// (round-6 verified layout: TSS=36, scalar fragment loads, double buffered)
#define TBM 128
#define TBN 128
#define TBK 32
#define TSS 36
#define GEMM_SMEM_BYTES (4 * TBM * TSS * 4)   // 2 bufs x (A,B) x 128x36 u32

__global__ __launch_bounds__(256) void k_tf32gemm(
    const float* __restrict__ A, const float* __restrict__ B,
    float* __restrict__ C, int M, int N, int K,
    const float* __restrict__ avs, const float* __restrict__ avd,
    float* __restrict__ as_out, float* __restrict__ ad_out, int heads)
{
    extern __shared__ unsigned smem_u[];
    unsigned* Abase = smem_u;                    // [2][TBM][TSS]
    unsigned* Bbase = smem_u + 2 * TBM * TSS;    // [2][TBN][TSS]

    int tid = threadIdx.x;
    int bm = blockIdx.y * TBM, bn = blockIdx.x * TBN;
    int wid = tid >> 5, lane = tid & 31;
    int wm = (wid >> 2) * 64;
    int wn = (wid & 3) * 32;
    int g  = lane >> 2;
    int t4 = lane & 3;

    int r0 = tid >> 3;
    int c4 = (tid & 7) * 4;

    float c[4][4][4];
    #pragma unroll
    for (int i = 0; i < 4; i++)
        #pragma unroll
        for (int j = 0; j < 4; j++)
            #pragma unroll
            for (int r = 0; r < 4; r++) c[i][j][r] = 0.f;

    const float4 zero4 = make_float4(0.f, 0.f, 0.f, 0.f);
    float4 pa[4], pb[4];
    int nt = K / TBK;

    // fetch tile 0
    #pragma unroll
    for (int i = 0; i < 4; i++) {
        int ar = bm + r0 + 32 * i;
        pa[i] = (ar < M) ? *(const float4*)(A + (size_t)ar * K + c4) : zero4;
        int br = bn + r0 + 32 * i;
        pb[i] = (br < N) ? *(const float4*)(B + (size_t)br * K + c4) : zero4;
    }
    // store tile 0 -> buf 0
    {
        unsigned* Ab = Abase;
        unsigned* Bb = Bbase;
        #pragma unroll
        for (int i = 0; i < 4; i++) {
            int rr = r0 + 32 * i;
            Ab[rr * TSS + c4 + 0] = f2tf32(pa[i].x); Ab[rr * TSS + c4 + 1] = f2tf32(pa[i].y);
            Ab[rr * TSS + c4 + 2] = f2tf32(pa[i].z); Ab[rr * TSS + c4 + 3] = f2tf32(pa[i].w);
            Bb[rr * TSS + c4 + 0] = f2tf32(pb[i].x); Bb[rr * TSS + c4 + 1] = f2tf32(pb[i].y);
            Bb[rr * TSS + c4 + 2] = f2tf32(pb[i].z); Bb[rr * TSS + c4 + 3] = f2tf32(pb[i].w);
        }
    }
    __syncthreads();

    for (int t = 0; t < nt; t++) {
        int cur = t & 1;
        bool more = (t + 1 < nt);
        if (more) {
            int k0 = (t + 1) * TBK;
            #pragma unroll
            for (int i = 0; i < 4; i++) {
                int ar = bm + r0 + 32 * i;
                pa[i] = (ar < M) ? *(const float4*)(A + (size_t)ar * K + k0 + c4) : zero4;
                int br = bn + r0 + 32 * i;
                pb[i] = (br < N) ? *(const float4*)(B + (size_t)br * K + k0 + c4) : zero4;
            }
        }
        const unsigned* Ab = Abase + cur * TBM * TSS;
        const unsigned* Bb = Bbase + cur * TBM * TSS;
        #pragma unroll
        for (int ks = 0; ks < 4; ks++) {
            int k8 = ks * 8;
            unsigned af[4][4], bf[4][2];
            #pragma unroll
            for (int mt = 0; mt < 4; mt++) {
                int row = wm + mt * 16 + g;
                af[mt][0] = Ab[row * TSS + k8 + t4];
                af[mt][1] = Ab[(row + 8) * TSS + k8 + t4];
                af[mt][2] = Ab[row * TSS + k8 + t4 + 4];
                af[mt][3] = Ab[(row + 8) * TSS + k8 + t4 + 4];
            }
            #pragma unroll
            for (int ntj = 0; ntj < 4; ntj++) {
                int col = wn + ntj * 8 + g;
                bf[ntj][0] = Bb[col * TSS + k8 + t4];
                bf[ntj][1] = Bb[col * TSS + k8 + t4 + 4];
            }
            #pragma unroll
            for (int mt = 0; mt < 4; mt++)
                #pragma unroll
                for (int ntj = 0; ntj < 4; ntj++) {
                    asm volatile(
                        "mma.sync.aligned.m16n8k8.row.col.f32.tf32.tf32.f32 "
                        "{%0,%1,%2,%3}, {%4,%5,%6,%7}, {%8,%9}, {%0,%1,%2,%3};"
                        : "+f"(c[mt][ntj][0]), "+f"(c[mt][ntj][1]),
                          "+f"(c[mt][ntj][2]), "+f"(c[mt][ntj][3])
                        : "r"(af[mt][0]), "r"(af[mt][1]), "r"(af[mt][2]), "r"(af[mt][3]),
                          "r"(bf[ntj][0]), "r"(bf[ntj][1]));
                }
        }
        if (more) {
            int nx = cur ^ 1;
            unsigned* Aw = Abase + nx * TBM * TSS;
            unsigned* Bw = Bbase + nx * TBM * TSS;
            #pragma unroll
            for (int i = 0; i < 4; i++) {
                int rr = r0 + 32 * i;
                Aw[rr * TSS + c4 + 0] = f2tf32(pa[i].x); Aw[rr * TSS + c4 + 1] = f2tf32(pa[i].y);
                Aw[rr * TSS + c4 + 2] = f2tf32(pa[i].z); Aw[rr * TSS + c4 + 3] = f2tf32(pa[i].w);
                Bw[rr * TSS + c4 + 0] = f2tf32(pb[i].x); Bw[rr * TSS + c4 + 1] = f2tf32(pb[i].y);
                Bw[rr * TSS + c4 + 2] = f2tf32(pb[i].z); Bw[rr * TSS + c4 + 3] = f2tf32(pb[i].w);
            }
            __syncthreads();
        }
    }

    // ---- C store ----
    #pragma unroll
    for (int mt = 0; mt < 4; mt++) {
        int row0 = bm + wm + mt * 16 + g;
        #pragma unroll
        for (int ntj = 0; ntj < 4; ntj++) {
            int col = bn + wn + ntj * 8 + t4 * 2;
            if (row0 < M && col + 1 < N) {
                C[(size_t)row0 * N + col]     = c[mt][ntj][0];
                C[(size_t)row0 * N + col + 1] = c[mt][ntj][1];
            }
            if (row0 + 8 < M && col + 1 < N) {
                C[(size_t)(row0 + 8) * N + col]     = c[mt][ntj][2];
                C[(size_t)(row0 + 8) * N + col + 1] = c[mt][ntj][3];
            }
        }
    }

    // ---- fused attention-coefficient partials ----
    int head = (bn + wn) >> 6;
    if (head < heads) {
        float asac[4][2] = {}, adac[4][2] = {};
        #pragma unroll
        for (int mt = 0; mt < 4; mt++)
            #pragma unroll
            for (int ntj = 0; ntj < 4; ntj++) {
                int colb = bn + wn + ntj * 8 + t4 * 2;
                if (colb + 1 < N) {
                    float s0 = avs[colb], s1 = avs[colb + 1];
                    float d0 = avd[colb], d1 = avd[colb + 1];
                    asac[mt][0] += c[mt][ntj][0] * s0 + c[mt][ntj][1] * s1;
                    adac[mt][0] += c[mt][ntj][0] * d0 + c[mt][ntj][1] * d1;
                    asac[mt][1] += c[mt][ntj][2] * s0 + c[mt][ntj][3] * s1;
                    adac[mt][1] += c[mt][ntj][2] * d0 + c[mt][ntj][3] * d1;
                }
            }
        #pragma unroll
        for (int mt = 0; mt < 4; mt++)
            #pragma unroll
            for (int hf = 0; hf < 2; hf++) {
                float v = asac[mt][hf];
                float w = adac[mt][hf];
                v += __shfl_xor_sync(0xFFFFFFFFu, v, 1);
                v += __shfl_xor_sync(0xFFFFFFFFu, v, 2);
                w += __shfl_xor_sync(0xFFFFFFFFu, w, 1);
                w += __shfl_xor_sync(0xFFFFFFFFu, w, 2);
                int row = bm + wm + mt * 16 + g + hf * 8;
                if (t4 == 0 && row < M) {
                    atomicAdd(&as_out[row * heads + head], v);
                    atomicAdd(&ad_out[row * heads + head], w);
                }
            }
    }
}

// ---------------- softmax layer 1: warp per dst node, 4 heads ----------------
__global__ __launch_bounds__(256) void k_softmax1()
{
    int w = (blockIdx.x * blockDim.x + threadIdx.x) >> 5;
    int lane = threadIdx.x & 31;
    if (w >= NN) return;
    int beg = g_rowptr[w], end = g_rowptr[w + 1];
    const float4* as4 = (const float4*)g_as1;
    float4 adv = ((const float4*)g_ad1)[w];
    float4 mx = make_float4(-1e30f, -1e30f, -1e30f, -1e30f);
    for (int i = beg + lane; i < end; i += 32) {
        float4 e = as4[g_srcidx[i]];
        e.x += adv.x; e.y += adv.y; e.z += adv.z; e.w += adv.w;
        e.x = (e.x > 0.f) ? e.x : NEG_SLOPE * e.x;
        e.y = (e.y > 0.f) ? e.y : NEG_SLOPE * e.y;
        e.z = (e.z > 0.f) ? e.z : NEG_SLOPE * e.z;
        e.w = (e.w > 0.f) ? e.w : NEG_SLOPE * e.w;
        g_alpha1[i] = e;
        mx.x = fmaxf(mx.x, e.x); mx.y = fmaxf(mx.y, e.y);
        mx.z = fmaxf(mx.z, e.z); mx.w = fmaxf(mx.w, e.w);
    }
    #pragma unroll
    for (int o = 16; o > 0; o >>= 1) {
        mx.x = fmaxf(mx.x, __shfl_xor_sync(0xFFFFFFFFu, mx.x, o));
        mx.y = fmaxf(mx.y, __shfl_xor_sync(0xFFFFFFFFu, mx.y, o));
        mx.z = fmaxf(mx.z, __shfl_xor_sync(0xFFFFFFFFu, mx.z, o));
        mx.w = fmaxf(mx.w, __shfl_xor_sync(0xFFFFFFFFu, mx.w, o));
    }
    float4 sum = make_float4(0.f, 0.f, 0.f, 0.f);
    for (int i = beg + lane; i < end; i += 32) {
        float4 e = g_alpha1[i];
        e.x = __expf(e.x - mx.x); e.y = __expf(e.y - mx.y);
        e.z = __expf(e.z - mx.z); e.w = __expf(e.w - mx.w);
        g_alpha1[i] = e;
        sum.x += e.x; sum.y += e.y; sum.z += e.z; sum.w += e.w;
    }
    #pragma unroll
    for (int o = 16; o > 0; o >>= 1) {
        sum.x += __shfl_xor_sync(0xFFFFFFFFu, sum.x, o);
        sum.y += __shfl_xor_sync(0xFFFFFFFFu, sum.y, o);
        sum.z += __shfl_xor_sync(0xFFFFFFFFu, sum.z, o);
        sum.w += __shfl_xor_sync(0xFFFFFFFFu, sum.w, o);
    }
    if (lane == 0)
        g_rd1[w] = make_float4(1.f / sum.x, 1.f / sum.y, 1.f / sum.z, 1.f / sum.w);
}

// ---------------- softmax layer 2 --------------------------------------------
__global__ __launch_bounds__(256) void k_softmax2()
{
    int w = (blockIdx.x * blockDim.x + threadIdx.x) >> 5;
    int lane = threadIdx.x & 31;
    if (w >= NN) return;
    int beg = g_rowptr[w], end = g_rowptr[w + 1];
    float adv = g_ad2[w];
    float mx = -1e30f;
    for (int i = beg + lane; i < end; i += 32) {
        float e = g_as2[g_srcidx[i]] + adv;
        e = (e > 0.f) ? e : NEG_SLOPE * e;
        g_alpha2[i] = e;
        mx = fmaxf(mx, e);
    }
    #pragma unroll
    for (int o = 16; o > 0; o >>= 1)
        mx = fmaxf(mx, __shfl_xor_sync(0xFFFFFFFFu, mx, o));
    float sum = 0.f;
    for (int i = beg + lane; i < end; i += 32) {
        float e = __expf(g_alpha2[i] - mx);
        g_alpha2[i] = e;
        sum += e;
    }
    #pragma unroll
    for (int o = 16; o > 0; o >>= 1)
        sum += __shfl_xor_sync(0xFFFFFFFFu, sum, o);
    if (lane == 0) g_rd2[w] = 1.f / sum;
}

// ---- aggregation layer 1: 64 threads per dst row, fused +b1 and elu ---------
__global__ __launch_bounds__(256) void k_agg1(const float* __restrict__ b1)
{
    int row = blockIdx.x * 4 + (threadIdx.x >> 6);
    if (row >= NN) return;
    int q = threadIdx.x & 63;
    int head = q >> 4;
    int beg = g_rowptr[row], end = g_rowptr[row + 1];
    float4 rdv = g_rd1[row];
    float rd = (head == 0) ? rdv.x : (head == 1) ? rdv.y : (head == 2) ? rdv.z : rdv.w;
    float4 acc0 = make_float4(0.f, 0.f, 0.f, 0.f);
    float4 acc1 = make_float4(0.f, 0.f, 0.f, 0.f);
    int i = beg;
    for (; i + 2 <= end; i += 2) {
        int s0 = g_srcidx[i], s1 = g_srcidx[i + 1];
        float4 a40 = g_alpha1[i], a41 = g_alpha1[i + 1];
        float a0 = (head == 0) ? a40.x : (head == 1) ? a40.y : (head == 2) ? a40.z : a40.w;
        float a1 = (head == 0) ? a41.x : (head == 1) ? a41.y : (head == 2) ? a41.z : a41.w;
        float4 h0 = *(const float4*)(g_h1 + (size_t)s0 * HC1 + q * 4);
        float4 h1 = *(const float4*)(g_h1 + (size_t)s1 * HC1 + q * 4);
        acc0.x += a0 * h0.x; acc0.y += a0 * h0.y; acc0.z += a0 * h0.z; acc0.w += a0 * h0.w;
        acc1.x += a1 * h1.x; acc1.y += a1 * h1.y; acc1.z += a1 * h1.z; acc1.w += a1 * h1.w;
    }
    if (i < end) {
        int s0 = g_srcidx[i];
        float4 a40 = g_alpha1[i];
        float a0 = (head == 0) ? a40.x : (head == 1) ? a40.y : (head == 2) ? a40.z : a40.w;
        float4 h0 = *(const float4*)(g_h1 + (size_t)s0 * HC1 + q * 4);
        acc0.x += a0 * h0.x; acc0.y += a0 * h0.y; acc0.z += a0 * h0.z; acc0.w += a0 * h0.w;
    }
    float4 acc = make_float4((acc0.x + acc1.x) * rd, (acc0.y + acc1.y) * rd,
                             (acc0.z + acc1.z) * rd, (acc0.w + acc1.w) * rd);
    float4 bb = *(const float4*)(b1 + q * 4);
    acc.x += bb.x; acc.y += bb.y; acc.z += bb.z; acc.w += bb.w;
    acc.x = (acc.x > 0.f) ? acc.x : expm1f(acc.x);
    acc.y = (acc.y > 0.f) ? acc.y : expm1f(acc.y);
    acc.z = (acc.z > 0.f) ? acc.z : expm1f(acc.z);
    acc.w = (acc.w > 0.f) ? acc.w : expm1f(acc.w);
    *(float4*)(g_x2 + (size_t)row * HC1 + q * 4) = acc;
}

// ---- aggregation layer 2: 16 threads per dst row, fused +b2, writes d_out ---
__global__ __launch_bounds__(256) void k_agg2(const float* __restrict__ b2,
                                              float* __restrict__ out)
{
    int row = blockIdx.x * 16 + (threadIdx.x >> 4);
    if (row >= NN) return;
    int q = threadIdx.x & 15;
    int beg = g_rowptr[row], end = g_rowptr[row + 1];
    float rd = g_rd2[row];
    float4 acc0 = make_float4(0.f, 0.f, 0.f, 0.f);
    float4 acc1 = make_float4(0.f, 0.f, 0.f, 0.f);
    int i = beg;
    for (; i + 2 <= end; i += 2) {
        int s0 = g_srcidx[i], s1 = g_srcidx[i + 1];
        float a0 = g_alpha2[i], a1 = g_alpha2[i + 1];
        float4 h0 = *(const float4*)(g_h2 + (size_t)s0 * OC + q * 4);
        float4 h1 = *(const float4*)(g_h2 + (size_t)s1 * OC + q * 4);
        acc0.x += a0 * h0.x; acc0.y += a0 * h0.y; acc0.z += a0 * h0.z; acc0.w += a0 * h0.w;
        acc1.x += a1 * h1.x; acc1.y += a1 * h1.y; acc1.z += a1 * h1.z; acc1.w += a1 * h1.w;
    }
    if (i < end) {
        int s0 = g_srcidx[i];
        float a0 = g_alpha2[i];
        float4 h0 = *(const float4*)(g_h2 + (size_t)s0 * OC + q * 4);
        acc0.x += a0 * h0.x; acc0.y += a0 * h0.y; acc0.z += a0 * h0.z; acc0.w += a0 * h0.w;
    }
    float4 bb = *(const float4*)(b2 + q * 4);
    float4 acc = make_float4((acc0.x + acc1.x) * rd + bb.x, (acc0.y + acc1.y) * rd + bb.y,
                             (acc0.z + acc1.z) * rd + bb.z, (acc0.w + acc1.w) * rd + bb.w);
    *(float4*)(out + (size_t)row * OC + q * 4) = acc;
}

// =============================================================================
extern "C" void kernel_launch(void* const* d_in, const int* in_sizes, int n_in,
                              void* d_out, int out_size)
{
    const float* x     = (const float*)d_in[0];
    const int*   ei    = (const int*)d_in[1];
    const float* W1    = (const float*)d_in[2];
    const float* a_s1  = (const float*)d_in[3];
    const float* a_d1  = (const float*)d_in[4];
    const float* b1    = (const float*)d_in[5];
    const float* W2    = (const float*)d_in[6];
    const float* a_s2  = (const float*)d_in[7];
    const float* a_d2  = (const float*)d_in[8];
    const float* b2    = (const float*)d_in[9];
    float*       out   = (float*)d_out;

    float *h1, *x2, *as1, *ad1, *h2, *as2, *ad2;
    cudaGetSymbolAddress((void**)&h1,  g_h1);
    cudaGetSymbolAddress((void**)&x2,  g_x2);
    cudaGetSymbolAddress((void**)&as1, g_as1);
    cudaGetSymbolAddress((void**)&ad1, g_ad1);
    cudaGetSymbolAddress((void**)&h2,  g_h2);
    cudaGetSymbolAddress((void**)&as2, g_as2);
    cudaGetSymbolAddress((void**)&ad2, g_ad2);

    cudaFuncSetAttribute(k_tf32gemm,
                         cudaFuncAttributeMaxDynamicSharedMemorySize, GEMM_SMEM_BYTES);

    // ---- init + CSR build ----
    k_zero<<<(NN + 255) / 256, 256>>>();
    k_count<<<(EP + 255) / 256, 256>>>(ei);
    k_scan_all<<<1, SB_T>>>();
    k_scatter<<<(EP + 255) / 256, 256>>>(ei);

    // ---- layer 1 ----
    {
        dim3 grid((HC1 + TBN - 1) / TBN, (NN + TBM - 1) / TBM);
        k_tf32gemm<<<grid, 256, GEMM_SMEM_BYTES>>>(x, W1, h1, NN, HC1, INC,
                                                   a_s1, a_d1, as1, ad1, H1);
    }
    k_softmax1<<<(NN * 32 + 255) / 256, 256>>>();
    k_agg1<<<(NN + 3) / 4, 256>>>(b1);

    // ---- layer 2 ----
    {
        dim3 grid((OC + TBN - 1) / TBN, (NN + TBM - 1) / TBM);
        k_tf32gemm<<<grid, 256, GEMM_SMEM_BYTES>>>(x2, W2, h2, NN, OC, HC1,
                                                   a_s2, a_d2, as2, ad2, 1);
    }
    k_softmax2<<<(NN * 32 + 255) / 256, 256>>>();
    k_agg2<<<(NN + 15) / 16, 256>>>(b2, out);
}

// round 9
// speedup vs baseline: 1.3146x; 1.1499x over previous
#include <cuda_runtime.h>
#include <cuda_bf16.h>
#include <math.h>

// ---------------- problem constants ----------------
#define NN    50000
#define EE    800000
#define EP    850000          // EE + NN self loops
#define INC   1024
#define H1    4
#define C1    64
#define HC1   256             // H1*C1
#define OC    64
#define NEG_SLOPE 0.2f

#define SCAN_T 512
#define NTILES ((NN + SCAN_T - 1) / SCAN_T)

// ---------------- scratch (device globals) ----------------
__device__ float  g_h1[(size_t)NN * HC1];
__device__ float  g_x2[(size_t)NN * HC1];
__device__ float  g_as1[NN * H1];
__device__ float  g_ad1[NN * H1];
__device__ float4 g_alpha1[EP];               // per-edge exp values (4 heads), CSR order
__device__ float4 g_rd1[NN];                  // reciprocal softmax denominators

__device__ float  g_h2[(size_t)NN * OC];
__device__ float  g_as2[NN];
__device__ float  g_ad2[NN];
__device__ float  g_alpha2[EP];
__device__ float  g_rd2[NN];

// CSR
__device__ int g_deg[NN];
__device__ int g_rowptr[NN + 1];
__device__ int g_cursor[NN];
__device__ int g_srcidx[EP];
__device__ int g_bsum[NTILES];

__device__ __forceinline__ unsigned f2tf32(float f) {
    unsigned r;
    asm("cvt.rna.tf32.f32 %0, %1;" : "=r"(r) : "f"(f));
    return r;
}

// ================= init + CSR construction =================
__global__ void k_zero() {
    int i = blockIdx.x * blockDim.x + threadIdx.x;
    if (i >= NN) return;
    g_deg[i] = 0;
    g_as2[i] = 0.f; g_ad2[i] = 0.f;
    float4 z = make_float4(0.f, 0.f, 0.f, 0.f);
    ((float4*)g_as1)[i] = z;
    ((float4*)g_ad1)[i] = z;
}
__global__ void k_count(const int* __restrict__ ei) {
    int e = blockIdx.x * blockDim.x + threadIdx.x;
    if (e >= EP) return;
    int dn = (e < EE) ? ei[EE + e] : (e - EE);
    atomicAdd(&g_deg[dn], 1);
}
__global__ __launch_bounds__(SCAN_T) void k_scan1() {
    __shared__ int s[SCAN_T];
    int tid = threadIdx.x;
    int i = blockIdx.x * SCAN_T + tid;
    int v = (i < NN) ? g_deg[i] : 0;
    s[tid] = v;
    __syncthreads();
    #pragma unroll
    for (int off = 1; off < SCAN_T; off <<= 1) {
        int t = (tid >= off) ? s[tid - off] : 0;
        __syncthreads();
        s[tid] += t;
        __syncthreads();
    }
    if (i < NN) g_rowptr[i + 1] = s[tid];
    if (tid == SCAN_T - 1) g_bsum[blockIdx.x] = s[tid];
}
__global__ void k_scan2() {
    if (threadIdx.x == 0) {
        int run = 0;
        for (int t = 0; t < NTILES; t++) { int v = g_bsum[t]; g_bsum[t] = run; run += v; }
        g_rowptr[0] = 0;
    }
}
__global__ __launch_bounds__(SCAN_T) void k_scan3() {
    int i = blockIdx.x * SCAN_T + threadIdx.x;
    if (i < NN) g_rowptr[i + 1] += g_bsum[blockIdx.x];
}
__global__ void k_setcur() {
    int i = blockIdx.x * blockDim.x + threadIdx.x;
    if (i < NN) g_cursor[i] = g_rowptr[i];
}
__global__ void k_scatter(const int* __restrict__ ei) {
    int e = blockIdx.x * blockDim.x + threadIdx.x;
    if (e >= EP) return;
    int s, dn;
    if (e < EE) { s = ei[e]; dn = ei[EE + e]; }
    else        { s = e - EE; dn = s; }
    int pos = atomicAdd(&g_cursor[dn], 1);
    g_srcidx[pos] = s;
}

// ============= TF32 GEMM + fused attention-coefficient epilogue ==============
// (round-6 verified layout: TSS=36, scalar fragment loads, double buffered)
#define TBM 128
#define TBN 128
#define TBK 32
#define TSS 36
#define GEMM_SMEM_BYTES (4 * TBM * TSS * 4)

__global__ __launch_bounds__(256) void k_tf32gemm(
    const float* __restrict__ A, const float* __restrict__ B,
    float* __restrict__ C, int M, int N, int K,
    const float* __restrict__ avs, const float* __restrict__ avd,
    float* __restrict__ as_out, float* __restrict__ ad_out, int heads)
{
    extern __shared__ unsigned smem_u[];
    unsigned* Abase = smem_u;
    unsigned* Bbase = smem_u + 2 * TBM * TSS;

    int tid = threadIdx.x;
    int bm = blockIdx.y * TBM, bn = blockIdx.x * TBN;
    int wid = tid >> 5, lane = tid & 31;
    int wm = (wid >> 2) * 64;
    int wn = (wid & 3) * 32;
    int g  = lane >> 2;
    int t4 = lane & 3;

    int r0 = tid >> 3;
    int c4 = (tid & 7) * 4;

    float c[4][4][4];
    #pragma unroll
    for (int i = 0; i < 4; i++)
        #pragma unroll
        for (int j = 0; j < 4; j++)
            #pragma unroll
            for (int r = 0; r < 4; r++) c[i][j][r] = 0.f;

    const float4 zero4 = make_float4(0.f, 0.f, 0.f, 0.f);
    float4 pa[4], pb[4];
    int nt = K / TBK;

    #pragma unroll
    for (int i = 0; i < 4; i++) {
        int ar = bm + r0 + 32 * i;
        pa[i] = (ar < M) ? *(const float4*)(A + (size_t)ar * K + c4) : zero4;
        int br = bn + r0 + 32 * i;
        pb[i] = (br < N) ? *(const float4*)(B + (size_t)br * K + c4) : zero4;
    }
    {
        unsigned* Ab = Abase;
        unsigned* Bb = Bbase;
        #pragma unroll
        for (int i = 0; i < 4; i++) {
            int rr = r0 + 32 * i;
            Ab[rr * TSS + c4 + 0] = f2tf32(pa[i].x); Ab[rr * TSS + c4 + 1] = f2tf32(pa[i].y);
            Ab[rr * TSS + c4 + 2] = f2tf32(pa[i].z); Ab[rr * TSS + c4 + 3] = f2tf32(pa[i].w);
            Bb[rr * TSS + c4 + 0] = f2tf32(pb[i].x); Bb[rr * TSS + c4 + 1] = f2tf32(pb[i].y);
            Bb[rr * TSS + c4 + 2] = f2tf32(pb[i].z); Bb[rr * TSS + c4 + 3] = f2tf32(pb[i].w);
        }
    }
    __syncthreads();

    for (int t = 0; t < nt; t++) {
        int cur = t & 1;
        bool more = (t + 1 < nt);
        if (more) {
            int k0 = (t + 1) * TBK;
            #pragma unroll
            for (int i = 0; i < 4; i++) {
                int ar = bm + r0 + 32 * i;
                pa[i] = (ar < M) ? *(const float4*)(A + (size_t)ar * K + k0 + c4) : zero4;
                int br = bn + r0 + 32 * i;
                pb[i] = (br < N) ? *(const float4*)(B + (size_t)br * K + k0 + c4) : zero4;
            }
        }
        const unsigned* Ab = Abase + cur * TBM * TSS;
        const unsigned* Bb = Bbase + cur * TBM * TSS;
        #pragma unroll
        for (int ks = 0; ks < 4; ks++) {
            int k8 = ks * 8;
            unsigned af[4][4], bf[4][2];
            #pragma unroll
            for (int mt = 0; mt < 4; mt++) {
                int row = wm + mt * 16 + g;
                af[mt][0] = Ab[row * TSS + k8 + t4];
                af[mt][1] = Ab[(row + 8) * TSS + k8 + t4];
                af[mt][2] = Ab[row * TSS + k8 + t4 + 4];
                af[mt][3] = Ab[(row + 8) * TSS + k8 + t4 + 4];
            }
            #pragma unroll
            for (int ntj = 0; ntj < 4; ntj++) {
                int col = wn + ntj * 8 + g;
                bf[ntj][0] = Bb[col * TSS + k8 + t4];
                bf[ntj][1] = Bb[col * TSS + k8 + t4 + 4];
            }
            #pragma unroll
            for (int mt = 0; mt < 4; mt++)
                #pragma unroll
                for (int ntj = 0; ntj < 4; ntj++) {
                    asm volatile(
                        "mma.sync.aligned.m16n8k8.row.col.f32.tf32.tf32.f32 "
                        "{%0,%1,%2,%3}, {%4,%5,%6,%7}, {%8,%9}, {%0,%1,%2,%3};"
                        : "+f"(c[mt][ntj][0]), "+f"(c[mt][ntj][1]),
                          "+f"(c[mt][ntj][2]), "+f"(c[mt][ntj][3])
                        : "r"(af[mt][0]), "r"(af[mt][1]), "r"(af[mt][2]), "r"(af[mt][3]),
                          "r"(bf[ntj][0]), "r"(bf[ntj][1]));
                }
        }
        if (more) {
            int nx = cur ^ 1;
            unsigned* Aw = Abase + nx * TBM * TSS;
            unsigned* Bw = Bbase + nx * TBM * TSS;
            #pragma unroll
            for (int i = 0; i < 4; i++) {
                int rr = r0 + 32 * i;
                Aw[rr * TSS + c4 + 0] = f2tf32(pa[i].x); Aw[rr * TSS + c4 + 1] = f2tf32(pa[i].y);
                Aw[rr * TSS + c4 + 2] = f2tf32(pa[i].z); Aw[rr * TSS + c4 + 3] = f2tf32(pa[i].w);
                Bw[rr * TSS + c4 + 0] = f2tf32(pb[i].x); Bw[rr * TSS + c4 + 1] = f2tf32(pb[i].y);
                Bw[rr * TSS + c4 + 2] = f2tf32(pb[i].z); Bw[rr * TSS + c4 + 3] = f2tf32(pb[i].w);
            }
            __syncthreads();
        }
    }

    // ---- C store ----
    #pragma unroll
    for (int mt = 0; mt < 4; mt++) {
        int row0 = bm + wm + mt * 16 + g;
        #pragma unroll
        for (int ntj = 0; ntj < 4; ntj++) {
            int col = bn + wn + ntj * 8 + t4 * 2;
            if (row0 < M && col + 1 < N) {
                C[(size_t)row0 * N + col]     = c[mt][ntj][0];
                C[(size_t)row0 * N + col + 1] = c[mt][ntj][1];
            }
            if (row0 + 8 < M && col + 1 < N) {
                C[(size_t)(row0 + 8) * N + col]     = c[mt][ntj][2];
                C[(size_t)(row0 + 8) * N + col + 1] = c[mt][ntj][3];
            }
        }
    }

    // ---- fused attention-coefficient partials ----
    int head = (bn + wn) >> 6;
    if (head < heads) {
        float asac[4][2] = {}, adac[4][2] = {};
        #pragma unroll
        for (int mt = 0; mt < 4; mt++)
            #pragma unroll
            for (int ntj = 0; ntj < 4; ntj++) {
                int colb = bn + wn + ntj * 8 + t4 * 2;
                if (colb + 1 < N) {
                    float s0 = avs[colb], s1 = avs[colb + 1];
                    float d0 = avd[colb], d1 = avd[colb + 1];
                    asac[mt][0] += c[mt][ntj][0] * s0 + c[mt][ntj][1] * s1;
                    adac[mt][0] += c[mt][ntj][0] * d0 + c[mt][ntj][1] * d1;
                    asac[mt][1] += c[mt][ntj][2] * s0 + c[mt][ntj][3] * s1;
                    adac[mt][1] += c[mt][ntj][2] * d0 + c[mt][ntj][3] * d1;
                }
            }
        #pragma unroll
        for (int mt = 0; mt < 4; mt++)
            #pragma unroll
            for (int hf = 0; hf < 2; hf++) {
                float v = asac[mt][hf];
                float w = adac[mt][hf];
                v += __shfl_xor_sync(0xFFFFFFFFu, v, 1);
                v += __shfl_xor_sync(0xFFFFFFFFu, v, 2);
                w += __shfl_xor_sync(0xFFFFFFFFu, w, 1);
                w += __shfl_xor_sync(0xFFFFFFFFu, w, 2);
                int row = bm + wm + mt * 16 + g + hf * 8;
                if (t4 == 0 && row < M) {
                    atomicAdd(&as_out[row * heads + head], v);
                    atomicAdd(&ad_out[row * heads + head], w);
                }
            }
    }
}

// ---------------- softmax layer 1: warp per dst node, 4 heads ----------------
__global__ __launch_bounds__(256) void k_softmax1()
{
    int w = (blockIdx.x * blockDim.x + threadIdx.x) >> 5;
    int lane = threadIdx.x & 31;
    if (w >= NN) return;
    int beg = g_rowptr[w], end = g_rowptr[w + 1];
    const float4* as4 = (const float4*)g_as1;
    float4 adv = ((const float4*)g_ad1)[w];
    float4 mx = make_float4(-1e30f, -1e30f, -1e30f, -1e30f);
    for (int i = beg + lane; i < end; i += 32) {
        float4 e = as4[g_srcidx[i]];
        e.x += adv.x; e.y += adv.y; e.z += adv.z; e.w += adv.w;
        e.x = (e.x > 0.f) ? e.x : NEG_SLOPE * e.x;
        e.y = (e.y > 0.f) ? e.y : NEG_SLOPE * e.y;
        e.z = (e.z > 0.f) ? e.z : NEG_SLOPE * e.z;
        e.w = (e.w > 0.f) ? e.w : NEG_SLOPE * e.w;
        g_alpha1[i] = e;
        mx.x = fmaxf(mx.x, e.x); mx.y = fmaxf(mx.y, e.y);
        mx.z = fmaxf(mx.z, e.z); mx.w = fmaxf(mx.w, e.w);
    }
    #pragma unroll
    for (int o = 16; o > 0; o >>= 1) {
        mx.x = fmaxf(mx.x, __shfl_xor_sync(0xFFFFFFFFu, mx.x, o));
        mx.y = fmaxf(mx.y, __shfl_xor_sync(0xFFFFFFFFu, mx.y, o));
        mx.z = fmaxf(mx.z, __shfl_xor_sync(0xFFFFFFFFu, mx.z, o));
        mx.w = fmaxf(mx.w, __shfl_xor_sync(0xFFFFFFFFu, mx.w, o));
    }
    float4 sum = make_float4(0.f, 0.f, 0.f, 0.f);
    for (int i = beg + lane; i < end; i += 32) {
        float4 e = g_alpha1[i];
        e.x = __expf(e.x - mx.x); e.y = __expf(e.y - mx.y);
        e.z = __expf(e.z - mx.z); e.w = __expf(e.w - mx.w);
        g_alpha1[i] = e;
        sum.x += e.x; sum.y += e.y; sum.z += e.z; sum.w += e.w;
    }
    #pragma unroll
    for (int o = 16; o > 0; o >>= 1) {
        sum.x += __shfl_xor_sync(0xFFFFFFFFu, sum.x, o);
        sum.y += __shfl_xor_sync(0xFFFFFFFFu, sum.y, o);
        sum.z += __shfl_xor_sync(0xFFFFFFFFu, sum.z, o);
        sum.w += __shfl_xor_sync(0xFFFFFFFFu, sum.w, o);
    }
    if (lane == 0)
        g_rd1[w] = make_float4(1.f / sum.x, 1.f / sum.y, 1.f / sum.z, 1.f / sum.w);
}

// ---------------- softmax layer 2 --------------------------------------------
__global__ __launch_bounds__(256) void k_softmax2()
{
    int w = (blockIdx.x * blockDim.x + threadIdx.x) >> 5;
    int lane = threadIdx.x & 31;
    if (w >= NN) return;
    int beg = g_rowptr[w], end = g_rowptr[w + 1];
    float adv = g_ad2[w];
    float mx = -1e30f;
    for (int i = beg + lane; i < end; i += 32) {
        float e = g_as2[g_srcidx[i]] + adv;
        e = (e > 0.f) ? e : NEG_SLOPE * e;
        g_alpha2[i] = e;
        mx = fmaxf(mx, e);
    }
    #pragma unroll
    for (int o = 16; o > 0; o >>= 1)
        mx = fmaxf(mx, __shfl_xor_sync(0xFFFFFFFFu, mx, o));
    float sum = 0.f;
    for (int i = beg + lane; i < end; i += 32) {
        float e = __expf(g_alpha2[i] - mx);
        g_alpha2[i] = e;
        sum += e;
    }
    #pragma unroll
    for (int o = 16; o > 0; o >>= 1)
        sum += __shfl_xor_sync(0xFFFFFFFFu, sum, o);
    if (lane == 0) g_rd2[w] = 1.f / sum;
}

// ---- aggregation layer 1: 64 threads per dst row, fused +b1 and elu ---------
__global__ __launch_bounds__(256) void k_agg1(const float* __restrict__ b1)
{
    int row = blockIdx.x * 4 + (threadIdx.x >> 6);
    if (row >= NN) return;
    int q = threadIdx.x & 63;
    int head = q >> 4;
    int beg = g_rowptr[row], end = g_rowptr[row + 1];
    float4 rdv = g_rd1[row];
    float rd = (head == 0) ? rdv.x : (head == 1) ? rdv.y : (head == 2) ? rdv.z : rdv.w;
    float4 acc0 = make_float4(0.f, 0.f, 0.f, 0.f);
    float4 acc1 = make_float4(0.f, 0.f, 0.f, 0.f);
    int i = beg;
    for (; i + 2 <= end; i += 2) {
        int s0 = g_srcidx[i], s1 = g_srcidx[i + 1];
        float4 a40 = g_alpha1[i], a41 = g_alpha1[i + 1];
        float a0 = (head == 0) ? a40.x : (head == 1) ? a40.y : (head == 2) ? a40.z : a40.w;
        float a1 = (head == 0) ? a41.x : (head == 1) ? a41.y : (head == 2) ? a41.z : a41.w;
        float4 h0 = *(const float4*)(g_h1 + (size_t)s0 * HC1 + q * 4);
        float4 h1 = *(const float4*)(g_h1 + (size_t)s1 * HC1 + q * 4);
        acc0.x += a0 * h0.x; acc0.y += a0 * h0.y; acc0.z += a0 * h0.z; acc0.w += a0 * h0.w;
        acc1.x += a1 * h1.x; acc1.y += a1 * h1.y; acc1.z += a1 * h1.z; acc1.w += a1 * h1.w;
    }
    if (i < end) {
        int s0 = g_srcidx[i];
        float4 a40 = g_alpha1[i];
        float a0 = (head == 0) ? a40.x : (head == 1) ? a40.y : (head == 2) ? a40.z : a40.w;
        float4 h0 = *(const float4*)(g_h1 + (size_t)s0 * HC1 + q * 4);
        acc0.x += a0 * h0.x; acc0.y += a0 * h0.y; acc0.z += a0 * h0.z; acc0.w += a0 * h0.w;
    }
    float4 acc = make_float4((acc0.x + acc1.x) * rd, (acc0.y + acc1.y) * rd,
                             (acc0.z + acc1.z) * rd, (acc0.w + acc1.w) * rd);
    float4 bb = *(const float4*)(b1 + q * 4);
    acc.x += bb.x; acc.y += bb.y; acc.z += bb.z; acc.w += bb.w;
    acc.x = (acc.x > 0.f) ? acc.x : expm1f(acc.x);
    acc.y = (acc.y > 0.f) ? acc.y : expm1f(acc.y);
    acc.z = (acc.z > 0.f) ? acc.z : expm1f(acc.z);
    acc.w = (acc.w > 0.f) ? acc.w : expm1f(acc.w);
    *(float4*)(g_x2 + (size_t)row * HC1 + q * 4) = acc;
}

// ---- aggregation layer 2: 16 threads per dst row, fused +b2, writes d_out ---
__global__ __launch_bounds__(256) void k_agg2(const float* __restrict__ b2,
                                              float* __restrict__ out)
{
    int row = blockIdx.x * 16 + (threadIdx.x >> 4);
    if (row >= NN) return;
    int q = threadIdx.x & 15;
    int beg = g_rowptr[row], end = g_rowptr[row + 1];
    float rd = g_rd2[row];
    float4 acc0 = make_float4(0.f, 0.f, 0.f, 0.f);
    float4 acc1 = make_float4(0.f, 0.f, 0.f, 0.f);
    int i = beg;
    for (; i + 2 <= end; i += 2) {
        int s0 = g_srcidx[i], s1 = g_srcidx[i + 1];
        float a0 = g_alpha2[i], a1 = g_alpha2[i + 1];
        float4 h0 = *(const float4*)(g_h2 + (size_t)s0 * OC + q * 4);
        float4 h1 = *(const float4*)(g_h2 + (size_t)s1 * OC + q * 4);
        acc0.x += a0 * h0.x; acc0.y += a0 * h0.y; acc0.z += a0 * h0.z; acc0.w += a0 * h0.w;
        acc1.x += a1 * h1.x; acc1.y += a1 * h1.y; acc1.z += a1 * h1.z; acc1.w += a1 * h1.w;
    }
    if (i < end) {
        int s0 = g_srcidx[i];
        float a0 = g_alpha2[i];
        float4 h0 = *(const float4*)(g_h2 + (size_t)s0 * OC + q * 4);
        acc0.x += a0 * h0.x; acc0.y += a0 * h0.y; acc0.z += a0 * h0.z; acc0.w += a0 * h0.w;
    }
    float4 bb = *(const float4*)(b2 + q * 4);
    float4 acc = make_float4((acc0.x + acc1.x) * rd + bb.x, (acc0.y + acc1.y) * rd + bb.y,
                             (acc0.z + acc1.z) * rd + bb.z, (acc0.w + acc1.w) * rd + bb.w);
    *(float4*)(out + (size_t)row * OC + q * 4) = acc;
}

// =============================================================================
extern "C" void kernel_launch(void* const* d_in, const int* in_sizes, int n_in,
                              void* d_out, int out_size)
{
    const float* x     = (const float*)d_in[0];
    const int*   ei    = (const int*)d_in[1];
    const float* W1    = (const float*)d_in[2];
    const float* a_s1  = (const float*)d_in[3];
    const float* a_d1  = (const float*)d_in[4];
    const float* b1    = (const float*)d_in[5];
    const float* W2    = (const float*)d_in[6];
    const float* a_s2  = (const float*)d_in[7];
    const float* a_d2  = (const float*)d_in[8];
    const float* b2    = (const float*)d_in[9];
    float*       out   = (float*)d_out;

    float *h1, *x2, *as1, *ad1, *h2, *as2, *ad2;
    cudaGetSymbolAddress((void**)&h1,  g_h1);
    cudaGetSymbolAddress((void**)&x2,  g_x2);
    cudaGetSymbolAddress((void**)&as1, g_as1);
    cudaGetSymbolAddress((void**)&ad1, g_ad1);
    cudaGetSymbolAddress((void**)&h2,  g_h2);
    cudaGetSymbolAddress((void**)&as2, g_as2);
    cudaGetSymbolAddress((void**)&ad2, g_ad2);

    cudaFuncSetAttribute(k_tf32gemm,
                         cudaFuncAttributeMaxDynamicSharedMemorySize, GEMM_SMEM_BYTES);

    // ---- init + CSR build (multi-block scan; round-6 verified) ----
    k_zero<<<(NN + 255) / 256, 256>>>();
    k_count<<<(EP + 255) / 256, 256>>>(ei);
    k_scan1<<<NTILES, SCAN_T>>>();
    k_scan2<<<1, 32>>>();
    k_scan3<<<NTILES, SCAN_T>>>();
    k_setcur<<<(NN + 255) / 256, 256>>>();
    k_scatter<<<(EP + 255) / 256, 256>>>(ei);

    // ---- layer 1 ----
    {
        dim3 grid((HC1 + TBN - 1) / TBN, (NN + TBM - 1) / TBM);
        k_tf32gemm<<<grid, 256, GEMM_SMEM_BYTES>>>(x, W1, h1, NN, HC1, INC,
                                                   a_s1, a_d1, as1, ad1, H1);
    }
    k_softmax1<<<(NN * 32 + 255) / 256, 256>>>();
    k_agg1<<<(NN + 3) / 4, 256>>>(b1);

    // ---- layer 2 ----
    {
        dim3 grid((OC + TBN - 1) / TBN, (NN + TBM - 1) / TBM);
        k_tf32gemm<<<grid, 256, GEMM_SMEM_BYTES>>>(x2, W2, h2, NN, OC, HC1,
                                                   a_s2, a_d2, as2, ad2, 1);
    }
    k_softmax2<<<(NN * 32 + 255) / 256, 256>>>();
    k_agg2<<<(NN + 15) / 16, 256>>>(b2, out);
}